// round 2
// baseline (speedup 1.0000x reference)
#include <cuda_runtime.h>
#include <cuda_bf16.h>
#include <cstdint>

// ---------------------------------------------------------------------------
// Model_RNN: bidirectional RNN
//   B=64, T=512, F=768, E=100 -> I=868, H=64
//   1) xp[t,b,0:128] = concat(inputs, emb[pos]) @ [W_ih_f;W_ih_b]^T + biases
//   2) fwd/bwd tanh-RNN scans over T=512
//   3) head: Linear(128->32) -> LayerNorm -> ReLU -> Linear(32->4)
// ---------------------------------------------------------------------------

#define BATCH 64
#define TT    512
#define FEAT  768
#define EDIM  100
#define KDIM  868
#define HID   64
#define NTOK  (BATCH * TT)       // 32768

// scratch (device globals — no runtime allocation allowed)
__device__ float g_xp[NTOK * 128];   // [token(b*512+t)][128]  (0:64 fwd, 64:128 bwd)
__device__ float g_h [NTOK * 128];   // [b][t][128] = concat(h_f, h_b)

// ---------------------------------------------------------------------------
// helpers
// ---------------------------------------------------------------------------
__device__ __forceinline__ float tf32r(float x) {
    uint32_t u;
    asm("cvt.rna.tf32.f32 %0, %1;" : "=r"(u) : "f"(x));
    return __uint_as_float(u);
}

__device__ __forceinline__ void mma_tf32(float* c, const uint32_t* a, const uint32_t* b) {
    asm volatile(
        "mma.sync.aligned.m16n8k8.row.col.f32.tf32.tf32.f32 "
        "{%0,%1,%2,%3}, {%4,%5,%6,%7}, {%8,%9}, {%0,%1,%2,%3};\n"
        : "+f"(c[0]), "+f"(c[1]), "+f"(c[2]), "+f"(c[3])
        : "r"(a[0]), "r"(a[1]), "r"(a[2]), "r"(a[3]), "r"(b[0]), "r"(b[1]));
}

// ---------------------------------------------------------------------------
// Kernel 1: input projection GEMM  (M=32768, N=128, K=868) in tf32 mma.sync
// grid 256 CTAs (128 rows each), block 256 (8 warps, warp tile 32x64)
// ---------------------------------------------------------------------------
__global__ __launch_bounds__(256, 2)
void gemm1_kernel(const float* __restrict__ inp, const int* __restrict__ posi,
                  const float* __restrict__ emb,
                  const float* __restrict__ Wf, const float* __restrict__ Wb,
                  const float* __restrict__ bihf, const float* __restrict__ bhhf,
                  const float* __restrict__ bihb, const float* __restrict__ bhhb)
{
    __shared__ float As[128][36];    // padded: bank-conflict-free frag loads
    __shared__ float Bs[32][136];
    __shared__ float bias_s[128];

    const int tid  = threadIdx.x;
    const int m0   = blockIdx.x * 128;
    const int lane = tid & 31;
    const int warp = tid >> 5;
    const int wm   = warp >> 1;      // 0..3 (M)
    const int wn   = warp & 1;       // 0..1 (N)
    const int g    = lane >> 2;      // 0..7
    const int t4   = lane & 3;       // 0..3

    if (tid < 128)
        bias_s[tid] = (tid < 64) ? (bihf[tid] + bhhf[tid])
                                 : (bihb[tid - 64] + bhhb[tid - 64]);

    // detect int64 vs int32 pos layout (JAX x64 ambiguity). For int64 LE the
    // odd 32-bit words are all zero; for int32 that is (1/512)^32-improbable.
    bool p64;
    {
        int odd  = posi[2 * lane + 1];
        int even = posi[2 * lane];
        bool z = (odd == 0) && (even >= 0) && (even < 512);
        p64 = (__ballot_sync(0xffffffffu, z) == 0xffffffffu);
    }

    float c[2][8][4];
    #pragma unroll
    for (int mt = 0; mt < 2; mt++)
        #pragma unroll
        for (int nt = 0; nt < 8; nt++)
            #pragma unroll
            for (int i = 0; i < 4; i++) c[mt][nt][i] = 0.f;

    for (int ch = 0; ch < 28; ch++) {        // 28*32 = 896 >= 868 (zero-pad)
        const int kc = ch * 32;
        __syncthreads();
        // ---- stage A tile (128 x 32) ----
        if (ch < 24) {                        // pure `inputs` region (k < 768)
            #pragma unroll
            for (int i = 0; i < 4; i++) {
                int lin = tid + i * 256;      // float4 index; 1024 total
                int row = lin >> 3, c4 = lin & 7;
                float4 v = *(const float4*)(inp + (size_t)(m0 + row) * FEAT + kc + c4 * 4);
                float4 w;
                w.x = tf32r(v.x); w.y = tf32r(v.y); w.z = tf32r(v.z); w.w = tf32r(v.w);
                *(float4*)&As[row][c4 * 4] = w;
            }
        } else {                              // embedding gather region
            int ec0 = kc - FEAT;
            #pragma unroll
            for (int i = 0; i < 16; i++) {
                int lin = tid + i * 256;
                int row = lin >> 5, cc = lin & 31;
                int ecol = ec0 + cc;
                float v = 0.f;
                if (ecol < EDIM) {
                    int m = m0 + row;
                    int idx = p64 ? posi[2 * m] : posi[m];
                    idx &= 511;
                    v = emb[idx * EDIM + ecol];
                }
                As[row][cc] = tf32r(v);
            }
        }
        // ---- stage B tile (32 x 128): Bs[k][n] = Wc[n][kc+k] ----
        #pragma unroll
        for (int i = 0; i < 16; i++) {
            int lin = tid + i * 256;
            int kk = lin >> 7, n = lin & 127;
            int kg = kc + kk;
            float v = 0.f;
            if (kg < KDIM)
                v = (n < 64) ? Wf[n * KDIM + kg] : Wb[(n - 64) * KDIM + kg];
            Bs[kk][n] = tf32r(v);
        }
        __syncthreads();
        // ---- compute: 4 k-steps of 8 ----
        #pragma unroll
        for (int ks = 0; ks < 4; ks++) {
            const int kb = ks * 8;
            uint32_t a[2][4], bb[8][2];
            #pragma unroll
            for (int mt = 0; mt < 2; mt++) {
                int r = wm * 32 + mt * 16 + g;
                a[mt][0] = __float_as_uint(As[r    ][kb + t4]);
                a[mt][1] = __float_as_uint(As[r + 8][kb + t4]);
                a[mt][2] = __float_as_uint(As[r    ][kb + t4 + 4]);
                a[mt][3] = __float_as_uint(As[r + 8][kb + t4 + 4]);
            }
            #pragma unroll
            for (int nt = 0; nt < 8; nt++) {
                int cn = wn * 64 + nt * 8 + g;
                bb[nt][0] = __float_as_uint(Bs[kb + t4    ][cn]);
                bb[nt][1] = __float_as_uint(Bs[kb + t4 + 4][cn]);
            }
            #pragma unroll
            for (int mt = 0; mt < 2; mt++)
                #pragma unroll
                for (int nt = 0; nt < 8; nt++)
                    mma_tf32(c[mt][nt], a[mt], bb[nt]);
        }
    }
    // ---- epilogue: + bias, store to g_xp[token][n] ----
    #pragma unroll
    for (int mt = 0; mt < 2; mt++) {
        int r = m0 + wm * 32 + mt * 16 + g;
        #pragma unroll
        for (int nt = 0; nt < 8; nt++) {
            int cn = wn * 64 + nt * 8 + 2 * t4;
            g_xp[(size_t)r * 128 + cn]           = c[mt][nt][0] + bias_s[cn];
            g_xp[(size_t)r * 128 + cn + 1]       = c[mt][nt][1] + bias_s[cn + 1];
            g_xp[(size_t)(r + 8) * 128 + cn]     = c[mt][nt][2] + bias_s[cn];
            g_xp[(size_t)(r + 8) * 128 + cn + 1] = c[mt][nt][3] + bias_s[cn + 1];
        }
    }
}

// ---------------------------------------------------------------------------
// Kernel 2: RNN scans. 128 CTAs = (batch 64) x (dir 2), 64 threads each.
// Thread j owns W_hh row j in registers; h state ping-pongs in smem.
// ---------------------------------------------------------------------------
__global__ __launch_bounds__(64, 8)
void scan_kernel(const float* __restrict__ Whf, const float* __restrict__ Whb)
{
    const int pair = blockIdx.x;
    const int b = pair >> 1, dir = pair & 1;
    const int j = threadIdx.x;

    const float* W = dir ? Whb : Whf;
    float w[64];
    #pragma unroll
    for (int k = 0; k < 64; k += 4) {
        float4 v = *(const float4*)(W + j * 64 + k);
        w[k] = v.x; w[k + 1] = v.y; w[k + 2] = v.z; w[k + 3] = v.w;
    }

    __shared__ float hbuf[2][64];
    hbuf[0][j] = 0.f;
    __syncthreads();

    const float* xpb = g_xp + (size_t)b * TT * 128 + dir * 64 + j;
    float*       ob  = g_h  + (size_t)b * TT * 128 + dir * 64 + j;

    // depth-4 register prefetch queue (xp should be L2-resident)
    float xq[4];
    #pragma unroll
    for (int i = 0; i < 4; i++) {
        int t = dir ? (TT - 1 - i) : i;
        xq[i] = __ldg(xpb + (size_t)t * 128);
    }

    int p = 0;
    for (int s8 = 0; s8 < TT / 4; s8++) {
        #pragma unroll
        for (int u = 0; u < 4; u++) {
            const int s = s8 * 4 + u;
            float x = xq[u];
            const int sp = s + 4;
            if (sp < TT) {
                int tp = dir ? (TT - 1 - sp) : sp;
                xq[u] = __ldg(xpb + (size_t)tp * 128);
            }
            float a0 = 0.f, a1 = 0.f, a2 = 0.f, a3 = 0.f;
            const float* hp = hbuf[p];
            #pragma unroll
            for (int k = 0; k < 64; k += 4) {
                float4 hv = *(const float4*)(hp + k);
                a0 = fmaf(w[k],     hv.x, a0);
                a1 = fmaf(w[k + 1], hv.y, a1);
                a2 = fmaf(w[k + 2], hv.z, a2);
                a3 = fmaf(w[k + 3], hv.w, a3);
            }
            float h = tanhf(x + ((a0 + a1) + (a2 + a3)));
            hbuf[p ^ 1][j] = h;
            int t = dir ? (TT - 1 - s) : s;
            ob[(size_t)t * 128] = h;
            __syncthreads();
            p ^= 1;
        }
    }
}

// ---------------------------------------------------------------------------
// Kernel 3: head GEMM(128->32) + LayerNorm + ReLU + GEMM(32->4), fused.
// 256 CTAs x 128 tokens; block 256; thread tile 4 tokens x 4 outputs.
// dynamic smem: As[128][132] + W1t[128][36] + h1s[128][33] + small = ~104 KB
// ---------------------------------------------------------------------------
#define HEAD_SMEM_FLOATS (128*132 + 128*36 + 128*33 + 128 + 32*3 + 4)

__global__ __launch_bounds__(256, 2)
void head_kernel(const float* __restrict__ W1, const float* __restrict__ b1,
                 const float* __restrict__ gamma, const float* __restrict__ beta,
                 const float* __restrict__ W2, const float* __restrict__ b2,
                 float* __restrict__ out)
{
    extern __shared__ float sm[];
    float* As  = sm;                    // [k][m]  128 x 132
    float* W1t = As + 128 * 132;        // [k][n]  128 x 36
    float* h1s = W1t + 128 * 36;        // [m][n]  128 x 33
    float* W2s = h1s + 128 * 33;        // 128
    float* b1s = W2s + 128;             // 32
    float* gms = b1s + 32;              // 32
    float* bts = gms + 32;              // 32
    float* b2s = bts + 32;              // 4

    const int tid = threadIdx.x;
    const int t0  = blockIdx.x * 128;

    #pragma unroll
    for (int i = 0; i < 16; i++) {      // W1t[k][n] = W1[n][k]
        int lin = tid + i * 256;
        int k = lin & 127, n = lin >> 7;
        W1t[k * 36 + n] = W1[n * 128 + k];
    }
    if (tid < 128) W2s[tid] = W2[tid];
    if (tid < 32) { b1s[tid] = b1[tid]; gms[tid] = gamma[tid]; bts[tid] = beta[tid]; }
    if (tid < 4)  b2s[tid] = b2[tid];

    #pragma unroll
    for (int i = 0; i < 16; i++) {      // As[k][m] = g_h[t0+m][k]
        int lin = tid + i * 256;
        int m = lin & 127, k4 = lin >> 7;   // k4: 0..31
        float4 v = *(const float4*)(g_h + (size_t)(t0 + m) * 128 + k4 * 4);
        As[(k4 * 4 + 0) * 132 + m] = v.x;
        As[(k4 * 4 + 1) * 132 + m] = v.y;
        As[(k4 * 4 + 2) * 132 + m] = v.z;
        As[(k4 * 4 + 3) * 132 + m] = v.w;
    }
    __syncthreads();

    const int tt = tid >> 3;            // 0..31 -> tokens tt*4..+3
    const int ot = tid & 7;             // 0..7  -> outputs ot*4..+3
    float acc[4][4];
    #pragma unroll
    for (int i = 0; i < 4; i++)
        #pragma unroll
        for (int jx = 0; jx < 4; jx++) acc[i][jx] = 0.f;

    #pragma unroll 8
    for (int k = 0; k < 128; k++) {
        float4 av = *(const float4*)(As + k * 132 + tt * 4);
        float4 bv = *(const float4*)(W1t + k * 36 + ot * 4);
        acc[0][0] = fmaf(av.x, bv.x, acc[0][0]); acc[0][1] = fmaf(av.x, bv.y, acc[0][1]);
        acc[0][2] = fmaf(av.x, bv.z, acc[0][2]); acc[0][3] = fmaf(av.x, bv.w, acc[0][3]);
        acc[1][0] = fmaf(av.y, bv.x, acc[1][0]); acc[1][1] = fmaf(av.y, bv.y, acc[1][1]);
        acc[1][2] = fmaf(av.y, bv.z, acc[1][2]); acc[1][3] = fmaf(av.y, bv.w, acc[1][3]);
        acc[2][0] = fmaf(av.z, bv.x, acc[2][0]); acc[2][1] = fmaf(av.z, bv.y, acc[2][1]);
        acc[2][2] = fmaf(av.z, bv.z, acc[2][2]); acc[2][3] = fmaf(av.z, bv.w, acc[2][3]);
        acc[3][0] = fmaf(av.w, bv.x, acc[3][0]); acc[3][1] = fmaf(av.w, bv.y, acc[3][1]);
        acc[3][2] = fmaf(av.w, bv.z, acc[3][2]); acc[3][3] = fmaf(av.w, bv.w, acc[3][3]);
    }
    #pragma unroll
    for (int i = 0; i < 4; i++)
        #pragma unroll
        for (int jx = 0; jx < 4; jx++)
            h1s[(tt * 4 + i) * 33 + ot * 4 + jx] = acc[i][jx] + b1s[ot * 4 + jx];
    __syncthreads();

    if (tid < 128) {
        float h[32];
        #pragma unroll
        for (int i = 0; i < 32; i++) h[i] = h1s[tid * 33 + i];
        float s1 = 0.f, s2 = 0.f;
        #pragma unroll
        for (int i = 0; i < 32; i++) { s1 += h[i]; s2 = fmaf(h[i], h[i], s2); }
        float mu  = s1 * (1.f / 32.f);
        float var = s2 * (1.f / 32.f) - mu * mu;
        float inv = rsqrtf(var + 1e-5f);
        float o0 = b2s[0], o1 = b2s[1], o2 = b2s[2], o3 = b2s[3];
        #pragma unroll
        for (int i = 0; i < 32; i++) {
            float r = fmaf((h[i] - mu) * inv, gms[i], bts[i]);
            r = fmaxf(r, 0.f);
            o0 = fmaf(W2s[i],      r, o0);
            o1 = fmaf(W2s[32 + i], r, o1);
            o2 = fmaf(W2s[64 + i], r, o2);
            o3 = fmaf(W2s[96 + i], r, o3);
        }
        float4 ov = make_float4(o0, o1, o2, o3);
        *(float4*)(out + (size_t)(t0 + tid) * 4) = ov;
    }
}

// ---------------------------------------------------------------------------
extern "C" void kernel_launch(void* const* d_in, const int* in_sizes, int n_in,
                              void* d_out, int out_size)
{
    const float* inputs = (const float*)d_in[0];
    const int*   posi   = (const int*)  d_in[1];
    const float* emb    = (const float*)d_in[2];
    const float* Wihf   = (const float*)d_in[3];
    const float* Whhf   = (const float*)d_in[4];
    const float* bihf   = (const float*)d_in[5];
    const float* bhhf   = (const float*)d_in[6];
    const float* Wihb   = (const float*)d_in[7];
    const float* Whhb   = (const float*)d_in[8];
    const float* bihb   = (const float*)d_in[9];
    const float* bhhb   = (const float*)d_in[10];
    const float* W1     = (const float*)d_in[11];
    const float* b1     = (const float*)d_in[12];
    const float* gamma  = (const float*)d_in[13];
    const float* beta   = (const float*)d_in[14];
    const float* W2     = (const float*)d_in[15];
    const float* b2     = (const float*)d_in[16];
    float* out = (float*)d_out;

    const int head_smem = HEAD_SMEM_FLOATS * (int)sizeof(float);
    cudaFuncSetAttribute(head_kernel, cudaFuncAttributeMaxDynamicSharedMemorySize, head_smem);

    gemm1_kernel<<<256, 256>>>(inputs, posi, emb, Wihf, Wihb, bihf, bhhf, bihb, bhhb);
    scan_kernel<<<128, 64>>>(Whhf, Whhb);
    head_kernel<<<256, 256, head_smem>>>(W1, b1, gamma, beta, W2, b2, out);
}

// round 3
// speedup vs baseline: 1.5233x; 1.5233x over previous
#include <cuda_runtime.h>
#include <cuda_bf16.h>
#include <cstdint>

// ---------------------------------------------------------------------------
// Model_RNN: bidirectional RNN
//   B=64, T=512, F=768, E=100 -> I=868, H=64
//   0) prep: embproj[v][n] = emb[v]@W_e[n]^T + bias_n ; g_Wt = tf32(W[:, :768])
//   1) xp = inputs @ W[:, :768]^T  (tf32 mma, cp.async pipelined) + embproj[pos]
//   2) fwd/bwd tanh-RNN scans over T=512 (pair-split dot)
//   3) head: Linear(128->32) -> LayerNorm -> ReLU -> Linear(32->4)
// ---------------------------------------------------------------------------

#define BATCH 64
#define TT    512
#define FEAT  768
#define EDIM  100
#define KDIM  868
#define NTOK  (BATCH * TT)       // 32768

// scratch (device globals — no runtime allocation allowed)
__device__ float g_xp[NTOK * 128];       // [token][128] (0:64 fwd, 64:128 bwd)
__device__ float g_h [NTOK * 128];       // [b][t][128] = concat(h_f, h_b)
__device__ float g_Wt[128 * FEAT];       // tf32-rounded W_ih rows (n major)
__device__ float g_embproj[512 * 128];   // emb @ W_e^T + (b_ih + b_hh)

// ---------------------------------------------------------------------------
// helpers
// ---------------------------------------------------------------------------
__device__ __forceinline__ float tf32r(float x) {
    uint32_t u;
    asm("cvt.rna.tf32.f32 %0, %1;" : "=r"(u) : "f"(x));
    return __uint_as_float(u);
}
__device__ __forceinline__ uint32_t tf32u(float x) {
    uint32_t u;
    asm("cvt.rna.tf32.f32 %0, %1;" : "=r"(u) : "f"(x));
    return u;
}
__device__ __forceinline__ void cpa16(void* sdst, const void* gsrc) {
    uint32_t s = (uint32_t)__cvta_generic_to_shared(sdst);
    asm volatile("cp.async.cg.shared.global [%0], [%1], 16;\n" :: "r"(s), "l"(gsrc));
}
__device__ __forceinline__ void mma_tf32(float* c, const uint32_t* a, const uint32_t* b) {
    asm volatile(
        "mma.sync.aligned.m16n8k8.row.col.f32.tf32.tf32.f32 "
        "{%0,%1,%2,%3}, {%4,%5,%6,%7}, {%8,%9}, {%0,%1,%2,%3};\n"
        : "+f"(c[0]), "+f"(c[1]), "+f"(c[2]), "+f"(c[3])
        : "r"(a[0]), "r"(a[1]), "r"(a[2]), "r"(a[3]), "r"(b[0]), "r"(b[1]));
}

// ---------------------------------------------------------------------------
// Kernel 0: prep. blocks 0..511 -> embproj row v; blocks 512..639 -> round W.
// ---------------------------------------------------------------------------
__global__ __launch_bounds__(128)
void prep_kernel(const float* __restrict__ emb,
                 const float* __restrict__ Wf, const float* __restrict__ Wb,
                 const float* __restrict__ bihf, const float* __restrict__ bhhf,
                 const float* __restrict__ bihb, const float* __restrict__ bhhb)
{
    const int bid = blockIdx.x, tid = threadIdx.x;
    if (bid < 512) {
        __shared__ float es[EDIM];
        if (tid < EDIM) es[tid] = emb[bid * EDIM + tid];
        __syncthreads();
        const int n = tid;
        const float* wr = (n < 64) ? (Wf + n * KDIM + FEAT)
                                   : (Wb + (n - 64) * KDIM + FEAT);
        float acc = (n < 64) ? (bihf[n] + bhhf[n]) : (bihb[n - 64] + bhhb[n - 64]);
        #pragma unroll 4
        for (int e = 0; e < EDIM; e++) acc = fmaf(es[e], wr[e], acc);
        g_embproj[bid * 128 + n] = acc;
    } else {
        const int n = bid - 512;   // 0..127
        const float* wr = (n < 64) ? (Wf + n * KDIM) : (Wb + (n - 64) * KDIM);
        #pragma unroll
        for (int k = tid; k < FEAT; k += 128)
            g_Wt[n * FEAT + k] = tf32r(wr[k]);
    }
}

// ---------------------------------------------------------------------------
// Kernel 1: pipelined tf32 GEMM  (M=32768, N=128, K=768)
// grid 256 CTAs (128 rows), block 256 (8 warps, warp tile 32x64), 3-stage cp.async
// smem layout: As[s][row][36] row-major k-slice; Bs[s][n][36] (k contiguous)
// ---------------------------------------------------------------------------
#define STG   3
#define TILEF (128 * 36)
#define CH_N  (FEAT / 32)   // 24

__global__ __launch_bounds__(256, 2)
void gemm1_kernel(const float* __restrict__ inp, const int* __restrict__ posi)
{
    extern __shared__ float sm[];
    float* As = sm;                // [STG][TILEF]
    float* Bs = sm + STG * TILEF;  // [STG][TILEF]

    const int tid  = threadIdx.x;
    const int m0   = blockIdx.x * 128;
    const int lane = tid & 31;
    const int warp = tid >> 5;
    const int wm   = warp >> 1;      // 0..3 (M)
    const int wn   = warp & 1;       // 0..1 (N)
    const int g    = lane >> 2;      // 0..7
    const int t4   = lane & 3;       // 0..3

    // detect int64 vs int32 pos layout (JAX x64 ambiguity)
    bool p64;
    {
        int odd  = posi[2 * lane + 1];
        int even = posi[2 * lane];
        bool z = (odd == 0) && (even >= 0) && (even < 512);
        p64 = (__ballot_sync(0xffffffffu, z) == 0xffffffffu);
    }

    auto stage = [&](int ch) {
        const int s = ch % STG;
        const float* asrc = inp + (size_t)m0 * FEAT + ch * 32;
        float* adst = As + s * TILEF;
        #pragma unroll
        for (int i = 0; i < 4; i++) {
            int lin = tid + i * 256;           // 1024 float4s
            int row = lin >> 3, c4 = lin & 7;
            cpa16(adst + row * 36 + c4 * 4, asrc + (size_t)row * FEAT + c4 * 4);
        }
        const float* bsrc = g_Wt + ch * 32;
        float* bdst = Bs + s * TILEF;
        #pragma unroll
        for (int i = 0; i < 4; i++) {
            int lin = tid + i * 256;
            int n = lin >> 3, c4 = lin & 7;
            cpa16(bdst + n * 36 + c4 * 4, bsrc + (size_t)n * FEAT + c4 * 4);
        }
    };

    float c[2][8][4];
    #pragma unroll
    for (int mt = 0; mt < 2; mt++)
        #pragma unroll
        for (int nt = 0; nt < 8; nt++)
            #pragma unroll
            for (int i = 0; i < 4; i++) c[mt][nt][i] = 0.f;

    stage(0); asm volatile("cp.async.commit_group;\n" ::: "memory");
    stage(1); asm volatile("cp.async.commit_group;\n" ::: "memory");

    for (int ch = 0; ch < CH_N; ch++) {
        asm volatile("cp.async.wait_group 1;\n" ::: "memory");
        __syncthreads();
        if (ch + 2 < CH_N) stage(ch + 2);
        asm volatile("cp.async.commit_group;\n" ::: "memory");

        const float* Ab = As + (ch % STG) * TILEF;
        const float* Bb = Bs + (ch % STG) * TILEF;
        #pragma unroll
        for (int ks = 0; ks < 4; ks++) {
            const int kb = ks * 8;
            uint32_t a[2][4], bb[8][2];
            #pragma unroll
            for (int mt = 0; mt < 2; mt++) {
                int r = wm * 32 + mt * 16 + g;
                a[mt][0] = tf32u(Ab[r * 36 + kb + t4]);
                a[mt][1] = tf32u(Ab[(r + 8) * 36 + kb + t4]);
                a[mt][2] = tf32u(Ab[r * 36 + kb + t4 + 4]);
                a[mt][3] = tf32u(Ab[(r + 8) * 36 + kb + t4 + 4]);
            }
            #pragma unroll
            for (int nt = 0; nt < 8; nt++) {
                int cn = wn * 64 + nt * 8 + g;
                bb[nt][0] = __float_as_uint(Bb[cn * 36 + kb + t4]);
                bb[nt][1] = __float_as_uint(Bb[cn * 36 + kb + t4 + 4]);
            }
            #pragma unroll
            for (int mt = 0; mt < 2; mt++)
                #pragma unroll
                for (int nt = 0; nt < 8; nt++)
                    mma_tf32(c[mt][nt], a[mt], bb[nt]);
        }
        __syncthreads();
    }

    // epilogue: + embproj[pos[row]] (bias folded in), store to g_xp
    #pragma unroll
    for (int mt = 0; mt < 2; mt++) {
        int r = m0 + wm * 32 + mt * 16 + g;
        int i0 = (p64 ? posi[2 * r] : posi[r]) & 511;
        int i1 = (p64 ? posi[2 * (r + 8)] : posi[r + 8]) & 511;
        const float* e0 = g_embproj + i0 * 128;
        const float* e1 = g_embproj + i1 * 128;
        #pragma unroll
        for (int nt = 0; nt < 8; nt++) {
            int cn = wn * 64 + nt * 8 + 2 * t4;
            g_xp[(size_t)r * 128 + cn]           = c[mt][nt][0] + e0[cn];
            g_xp[(size_t)r * 128 + cn + 1]       = c[mt][nt][1] + e0[cn + 1];
            g_xp[(size_t)(r + 8) * 128 + cn]     = c[mt][nt][2] + e1[cn];
            g_xp[(size_t)(r + 8) * 128 + cn + 1] = c[mt][nt][3] + e1[cn + 1];
        }
    }
}

// ---------------------------------------------------------------------------
// Kernel 2: RNN scans. 128 CTAs = (batch 64) x (dir 2), 128 threads each.
// Pair (2j, 2j+1) shares hidden row j; each half does 32 FMAs, shfl-combine.
// ---------------------------------------------------------------------------
__global__ __launch_bounds__(128, 8)
void scan_kernel(const float* __restrict__ Whf, const float* __restrict__ Whb)
{
    const int pair = blockIdx.x;
    const int b = pair >> 1, dir = pair & 1;
    const int tid  = threadIdx.x;
    const int j    = tid >> 1;     // hidden row 0..63
    const int half = tid & 1;      // which 32-wide k chunk

    const float* W = dir ? Whb : Whf;
    float w[32];
    #pragma unroll
    for (int k = 0; k < 32; k += 4) {
        float4 v = *(const float4*)(W + j * 64 + half * 32 + k);
        w[k] = v.x; w[k + 1] = v.y; w[k + 2] = v.z; w[k + 3] = v.w;
    }

    __shared__ float hbuf[2][64];
    if (tid < 64) hbuf[0][tid] = 0.f;
    __syncthreads();

    const float* xpb = g_xp + (size_t)b * TT * 128 + dir * 64 + j;
    float*       ob  = g_h  + (size_t)b * TT * 128 + dir * 64 + j;

    float xq[4];
    #pragma unroll
    for (int i = 0; i < 4; i++) {
        int t = dir ? (TT - 1 - i) : i;
        xq[i] = __ldg(xpb + (size_t)t * 128);
    }

    int p = 0;
    for (int s4 = 0; s4 < TT / 4; s4++) {
        #pragma unroll
        for (int u = 0; u < 4; u++) {
            const int s = s4 * 4 + u;
            float x = xq[u];
            const int sp = s + 4;
            if (sp < TT) {
                int tp = dir ? (TT - 1 - sp) : sp;
                xq[u] = __ldg(xpb + (size_t)tp * 128);
            }
            float a0 = 0.f, a1 = 0.f, a2 = 0.f, a3 = 0.f;
            const float* hp = hbuf[p] + half * 32;
            #pragma unroll
            for (int k = 0; k < 32; k += 4) {
                float4 hv = *(const float4*)(hp + k);
                a0 = fmaf(w[k],     hv.x, a0);
                a1 = fmaf(w[k + 1], hv.y, a1);
                a2 = fmaf(w[k + 2], hv.z, a2);
                a3 = fmaf(w[k + 3], hv.w, a3);
            }
            float a = (a0 + a1) + (a2 + a3);
            a += __shfl_xor_sync(0xffffffffu, a, 1);
            float h = tanhf(x + a);
            int t = dir ? (TT - 1 - s) : s;
            if (half == 0) hbuf[p ^ 1][j] = h;       // smem update
            else           ob[(size_t)t * 128] = h;  // global store (off crit path)
            __syncthreads();
            p ^= 1;
        }
    }
}

// ---------------------------------------------------------------------------
// Kernel 3: head GEMM(128->32) + LayerNorm + ReLU + GEMM(32->4), fused.
// ---------------------------------------------------------------------------
#define HEAD_SMEM_FLOATS (128*132 + 128*36 + 128*33 + 128 + 32*3 + 4)

__global__ __launch_bounds__(256, 2)
void head_kernel(const float* __restrict__ W1, const float* __restrict__ b1,
                 const float* __restrict__ gamma, const float* __restrict__ beta,
                 const float* __restrict__ W2, const float* __restrict__ b2,
                 float* __restrict__ out)
{
    extern __shared__ float sm[];
    float* As  = sm;                    // [k][m]  128 x 132
    float* W1t = As + 128 * 132;        // [k][n]  128 x 36
    float* h1s = W1t + 128 * 36;        // [m][n]  128 x 33
    float* W2s = h1s + 128 * 33;        // 128
    float* b1s = W2s + 128;             // 32
    float* gms = b1s + 32;              // 32
    float* bts = gms + 32;              // 32
    float* b2s = bts + 32;              // 4

    const int tid = threadIdx.x;
    const int t0  = blockIdx.x * 128;

    #pragma unroll
    for (int i = 0; i < 16; i++) {      // W1t[k][n] = W1[n][k]
        int lin = tid + i * 256;
        int k = lin & 127, n = lin >> 7;
        W1t[k * 36 + n] = W1[n * 128 + k];
    }
    if (tid < 128) W2s[tid] = W2[tid];
    if (tid < 32) { b1s[tid] = b1[tid]; gms[tid] = gamma[tid]; bts[tid] = beta[tid]; }
    if (tid < 4)  b2s[tid] = b2[tid];

    #pragma unroll
    for (int i = 0; i < 16; i++) {      // As[k][m] = g_h[t0+m][k]
        int lin = tid + i * 256;
        int m = lin & 127, k4 = lin >> 7;
        float4 v = *(const float4*)(g_h + (size_t)(t0 + m) * 128 + k4 * 4);
        As[(k4 * 4 + 0) * 132 + m] = v.x;
        As[(k4 * 4 + 1) * 132 + m] = v.y;
        As[(k4 * 4 + 2) * 132 + m] = v.z;
        As[(k4 * 4 + 3) * 132 + m] = v.w;
    }
    __syncthreads();

    const int tt = tid >> 3;
    const int ot = tid & 7;
    float acc[4][4];
    #pragma unroll
    for (int i = 0; i < 4; i++)
        #pragma unroll
        for (int jx = 0; jx < 4; jx++) acc[i][jx] = 0.f;

    #pragma unroll 8
    for (int k = 0; k < 128; k++) {
        float4 av = *(const float4*)(As + k * 132 + tt * 4);
        float4 bv = *(const float4*)(W1t + k * 36 + ot * 4);
        acc[0][0] = fmaf(av.x, bv.x, acc[0][0]); acc[0][1] = fmaf(av.x, bv.y, acc[0][1]);
        acc[0][2] = fmaf(av.x, bv.z, acc[0][2]); acc[0][3] = fmaf(av.x, bv.w, acc[0][3]);
        acc[1][0] = fmaf(av.y, bv.x, acc[1][0]); acc[1][1] = fmaf(av.y, bv.y, acc[1][1]);
        acc[1][2] = fmaf(av.y, bv.z, acc[1][2]); acc[1][3] = fmaf(av.y, bv.w, acc[1][3]);
        acc[2][0] = fmaf(av.z, bv.x, acc[2][0]); acc[2][1] = fmaf(av.z, bv.y, acc[2][1]);
        acc[2][2] = fmaf(av.z, bv.z, acc[2][2]); acc[2][3] = fmaf(av.z, bv.w, acc[2][3]);
        acc[3][0] = fmaf(av.w, bv.x, acc[3][0]); acc[3][1] = fmaf(av.w, bv.y, acc[3][1]);
        acc[3][2] = fmaf(av.w, bv.z, acc[3][2]); acc[3][3] = fmaf(av.w, bv.w, acc[3][3]);
    }
    #pragma unroll
    for (int i = 0; i < 4; i++)
        #pragma unroll
        for (int jx = 0; jx < 4; jx++)
            h1s[(tt * 4 + i) * 33 + ot * 4 + jx] = acc[i][jx] + b1s[ot * 4 + jx];
    __syncthreads();

    if (tid < 128) {
        float h[32];
        #pragma unroll
        for (int i = 0; i < 32; i++) h[i] = h1s[tid * 33 + i];
        float s1 = 0.f, s2 = 0.f;
        #pragma unroll
        for (int i = 0; i < 32; i++) { s1 += h[i]; s2 = fmaf(h[i], h[i], s2); }
        float mu  = s1 * (1.f / 32.f);
        float var = s2 * (1.f / 32.f) - mu * mu;
        float inv = rsqrtf(var + 1e-5f);
        float o0 = b2s[0], o1 = b2s[1], o2 = b2s[2], o3 = b2s[3];
        #pragma unroll
        for (int i = 0; i < 32; i++) {
            float r = fmaf((h[i] - mu) * inv, gms[i], bts[i]);
            r = fmaxf(r, 0.f);
            o0 = fmaf(W2s[i],      r, o0);
            o1 = fmaf(W2s[32 + i], r, o1);
            o2 = fmaf(W2s[64 + i], r, o2);
            o3 = fmaf(W2s[96 + i], r, o3);
        }
        *(float4*)(out + (size_t)(t0 + tid) * 4) = make_float4(o0, o1, o2, o3);
    }
}

// ---------------------------------------------------------------------------
extern "C" void kernel_launch(void* const* d_in, const int* in_sizes, int n_in,
                              void* d_out, int out_size)
{
    const float* inputs = (const float*)d_in[0];
    const int*   posi   = (const int*)  d_in[1];
    const float* emb    = (const float*)d_in[2];
    const float* Wihf   = (const float*)d_in[3];
    const float* Whhf   = (const float*)d_in[4];
    const float* bihf   = (const float*)d_in[5];
    const float* bhhf   = (const float*)d_in[6];
    const float* Wihb   = (const float*)d_in[7];
    const float* Whhb   = (const float*)d_in[8];
    const float* bihb   = (const float*)d_in[9];
    const float* bhhb   = (const float*)d_in[10];
    const float* W1     = (const float*)d_in[11];
    const float* b1     = (const float*)d_in[12];
    const float* gamma  = (const float*)d_in[13];
    const float* beta   = (const float*)d_in[14];
    const float* W2     = (const float*)d_in[15];
    const float* b2     = (const float*)d_in[16];
    float* out = (float*)d_out;

    const int gemm_smem = STG * 2 * TILEF * (int)sizeof(float);   // 110592
    cudaFuncSetAttribute(gemm1_kernel, cudaFuncAttributeMaxDynamicSharedMemorySize, gemm_smem);
    const int head_smem = HEAD_SMEM_FLOATS * (int)sizeof(float);
    cudaFuncSetAttribute(head_kernel, cudaFuncAttributeMaxDynamicSharedMemorySize, head_smem);

    prep_kernel<<<640, 128>>>(emb, Wihf, Wihb, bihf, bhhf, bihb, bhhb);
    gemm1_kernel<<<256, 256, gemm_smem>>>(inputs, posi);
    scan_kernel<<<128, 128>>>(Whhf, Whhb);
    head_kernel<<<256, 256, head_smem>>>(W1, b1, gamma, beta, W2, b2, out);
}

// round 6
// speedup vs baseline: 1.6122x; 1.0583x over previous
#include <cuda_runtime.h>
#include <cuda_fp16.h>
#include <cstdint>

// ---------------------------------------------------------------------------
// Model_RNN: bidirectional RNN
//   0) prep: embproj[v][n] = emb[v]@W_e[n]^T + bias_n ; g_Wh = half(W[:, :768])
//   1) xp = inputs @ W^T via fp16 mma.sync m16n8k16 (fp32 accum), 2-stage pipe
//   2) fwd/bwd tanh-RNN scans over T=512 (pair-split dot)
//   3) head: Linear(128->32) -> LayerNorm -> ReLU -> Linear(32->4)
// ---------------------------------------------------------------------------

#define BATCH 64
#define TT    512
#define FEAT  768
#define EDIM  100
#define KDIM  868
#define NTOK  (BATCH * TT)       // 32768

__device__ float  g_xp[NTOK * 128];      // [token][128] (0:64 fwd, 64:128 bwd)
__device__ float  g_h [NTOK * 128];      // [b][t][128] = concat(h_f, h_b)
__device__ __half g_Wh[128 * FEAT];      // half-rounded W_ih rows (n major)
__device__ float  g_embproj[512 * 128];  // emb @ W_e^T + (b_ih + b_hh)  (exact fp32)

// ---------------------------------------------------------------------------
// helpers
// ---------------------------------------------------------------------------
__device__ __forceinline__ void cpa16(void* sdst, const void* gsrc) {
    uint32_t s = (uint32_t)__cvta_generic_to_shared(sdst);
    asm volatile("cp.async.cg.shared.global [%0], [%1], 16;\n" :: "r"(s), "l"(gsrc));
}
__device__ __forceinline__ void mma_f16(float* c, const uint32_t* a, const uint32_t* b) {
    asm volatile(
        "mma.sync.aligned.m16n8k16.row.col.f32.f16.f16.f32 "
        "{%0,%1,%2,%3}, {%4,%5,%6,%7}, {%8,%9}, {%0,%1,%2,%3};\n"
        : "+f"(c[0]), "+f"(c[1]), "+f"(c[2]), "+f"(c[3])
        : "r"(a[0]), "r"(a[1]), "r"(a[2]), "r"(a[3]), "r"(b[0]), "r"(b[1]));
}

// ---------------------------------------------------------------------------
// Kernel 0: prep. blocks 0..511 -> embproj row v; blocks 512..639 -> W to half.
// ---------------------------------------------------------------------------
__global__ __launch_bounds__(128)
void prep_kernel(const float* __restrict__ emb,
                 const float* __restrict__ Wf, const float* __restrict__ Wb,
                 const float* __restrict__ bihf, const float* __restrict__ bhhf,
                 const float* __restrict__ bihb, const float* __restrict__ bhhb)
{
    const int bid = blockIdx.x, tid = threadIdx.x;
    if (bid < 512) {
        __shared__ float es[EDIM];
        if (tid < EDIM) es[tid] = emb[bid * EDIM + tid];
        __syncthreads();
        const int n = tid;
        const float* wr = (n < 64) ? (Wf + n * KDIM + FEAT)
                                   : (Wb + (n - 64) * KDIM + FEAT);
        float acc = (n < 64) ? (bihf[n] + bhhf[n]) : (bihb[n - 64] + bhhb[n - 64]);
        #pragma unroll 4
        for (int e = 0; e < EDIM; e++) acc = fmaf(es[e], wr[e], acc);
        g_embproj[bid * 128 + n] = acc;
    } else {
        const int n = bid - 512;   // 0..127
        const float* wr = (n < 64) ? (Wf + n * KDIM) : (Wb + (n - 64) * KDIM);
        #pragma unroll
        for (int k = tid; k < FEAT; k += 128)
            g_Wh[n * FEAT + k] = __float2half_rn(wr[k]);
    }
}

// ---------------------------------------------------------------------------
// Kernel 1: fp16 mma GEMM  (M=32768, N=128, K=768), fp32 accumulate.
// 256 CTAs x 128 M-rows; block 256 (8 warps: 4m x 2n, warp tile 32x64).
// K-chunk 32, double-buffered:
//   A: LDG fp32 (reg prefetch) -> cvt -> STS half   [128][40] halves
//   B: cp.async of pre-halved g_Wh                  [128][40] halves
// smem 40KB static -> 2 CTAs/SM.
// ---------------------------------------------------------------------------
#define GK    32
#define NCH   (FEAT / GK)    // 24
#define APAD  40             // halves per row (80B stride: conflict-free)

__global__ __launch_bounds__(256, 2)
void gemm1_kernel(const float* __restrict__ inp, const int* __restrict__ posi)
{
    __shared__ __half Asm[2][128 * APAD];
    __shared__ __half Bsm[2][128 * APAD];

    const int tid  = threadIdx.x;
    const int m0   = blockIdx.x * 128;
    const int lane = tid & 31;
    const int warp = tid >> 5;
    const int wm   = warp >> 1;      // 0..3 (M)
    const int wn   = warp & 1;       // 0..1 (N)
    const int g    = lane >> 2;      // 0..7
    const int t4   = lane & 3;       // 0..3

    // detect int64 vs int32 pos layout (JAX x64 ambiguity)
    bool p64;
    {
        int odd  = posi[2 * lane + 1];
        int even = posi[2 * lane];
        bool z = (odd == 0) && (even >= 0) && (even < 512);
        p64 = (__ballot_sync(0xffffffffu, z) == 0xffffffffu);
    }

    // A staging: 2 threads per row, 16 floats each
    const int ar = tid >> 1;             // row 0..127
    const int ac = (tid & 1) * 16;       // float col 0 / 16
    float4 areg[4];

    auto ldgA = [&](int ch) {
        const float* p = inp + (size_t)(m0 + ar) * FEAT + ch * GK + ac;
        areg[0] = __ldg((const float4*)(p + 0));
        areg[1] = __ldg((const float4*)(p + 4));
        areg[2] = __ldg((const float4*)(p + 8));
        areg[3] = __ldg((const float4*)(p + 12));
    };
    auto stsA = [&](int s) {
        __half2 hh[8];
        hh[0] = __floats2half2_rn(areg[0].x, areg[0].y);
        hh[1] = __floats2half2_rn(areg[0].z, areg[0].w);
        hh[2] = __floats2half2_rn(areg[1].x, areg[1].y);
        hh[3] = __floats2half2_rn(areg[1].z, areg[1].w);
        hh[4] = __floats2half2_rn(areg[2].x, areg[2].y);
        hh[5] = __floats2half2_rn(areg[2].z, areg[2].w);
        hh[6] = __floats2half2_rn(areg[3].x, areg[3].y);
        hh[7] = __floats2half2_rn(areg[3].z, areg[3].w);
        *(uint4*)&Asm[s][ar * APAD + ac]     = *(uint4*)&hh[0];
        *(uint4*)&Asm[s][ar * APAD + ac + 8] = *(uint4*)&hh[4];
    };
    auto stageB = [&](int ch) {
        const int s = ch & 1;
        #pragma unroll
        for (int i = 0; i < 2; i++) {
            int lin = tid + i * 256;          // 512 pieces of 8 halves
            int n = lin >> 2, c8 = lin & 3;
            cpa16(&Bsm[s][n * APAD + c8 * 8], g_Wh + (size_t)n * FEAT + ch * GK + c8 * 8);
        }
    };

    float c[2][8][4];
    #pragma unroll
    for (int mt = 0; mt < 2; mt++)
        #pragma unroll
        for (int nt = 0; nt < 8; nt++)
            #pragma unroll
            for (int i = 0; i < 4; i++) c[mt][nt][i] = 0.f;

    ldgA(0);
    stageB(0);
    asm volatile("cp.async.commit_group;\n" ::: "memory");

    for (int ch = 0; ch < NCH; ch++) {
        const int s = ch & 1;
        stsA(s);
        asm volatile("cp.async.wait_group 0;\n" ::: "memory");
        __syncthreads();
        if (ch + 1 < NCH) {
            ldgA(ch + 1);                       // in flight during compute
            stageB(ch + 1);
            asm volatile("cp.async.commit_group;\n" ::: "memory");
        }

        const __half* Ab = Asm[s];
        const __half* Bb = Bsm[s];
        #pragma unroll
        for (int ks = 0; ks < 2; ks++) {
            const int kb = ks * 16;
            uint32_t a[2][4], bb[8][2];
            #pragma unroll
            for (int mt = 0; mt < 2; mt++) {
                int r = wm * 32 + mt * 16 + g;
                int base = r * APAD + kb + t4 * 2;
                a[mt][0] = *(const uint32_t*)&Ab[base];
                a[mt][1] = *(const uint32_t*)&Ab[base + 8 * APAD];
                a[mt][2] = *(const uint32_t*)&Ab[base + 8];
                a[mt][3] = *(const uint32_t*)&Ab[base + 8 * APAD + 8];
            }
            #pragma unroll
            for (int nt = 0; nt < 8; nt++) {
                int cn = wn * 64 + nt * 8 + g;
                int bbase = cn * APAD + kb + t4 * 2;
                bb[nt][0] = *(const uint32_t*)&Bb[bbase];
                bb[nt][1] = *(const uint32_t*)&Bb[bbase + 8];
            }
            #pragma unroll
            for (int mt = 0; mt < 2; mt++)
                #pragma unroll
                for (int nt = 0; nt < 8; nt++)
                    mma_f16(c[mt][nt], a[mt], bb[nt]);
        }
        // single sync per iteration is sufficient: buffer written at iter ch+2
        // is only touched after sync(ch+1), which implies compute(ch) finished.
    }

    // epilogue: + embproj[pos[row]] (bias folded in), store to g_xp
    #pragma unroll
    for (int mt = 0; mt < 2; mt++) {
        int r = m0 + wm * 32 + mt * 16 + g;
        int i0 = (p64 ? posi[2 * r] : posi[r]) & 511;
        int i1 = (p64 ? posi[2 * (r + 8)] : posi[r + 8]) & 511;
        const float* e0 = g_embproj + i0 * 128;
        const float* e1 = g_embproj + i1 * 128;
        #pragma unroll
        for (int nt = 0; nt < 8; nt++) {
            int cn = wn * 64 + nt * 8 + 2 * t4;
            g_xp[(size_t)r * 128 + cn]           = c[mt][nt][0] + e0[cn];
            g_xp[(size_t)r * 128 + cn + 1]       = c[mt][nt][1] + e0[cn + 1];
            g_xp[(size_t)(r + 8) * 128 + cn]     = c[mt][nt][2] + e1[cn];
            g_xp[(size_t)(r + 8) * 128 + cn + 1] = c[mt][nt][3] + e1[cn + 1];
        }
    }
}

// ---------------------------------------------------------------------------
// Kernel 2: RNN scans. 128 CTAs = (batch 64) x (dir 2), 128 threads each.
// Pair (2j, 2j+1) shares hidden row j; each half does 32 FMAs, shfl-combine.
// ---------------------------------------------------------------------------
__global__ __launch_bounds__(128, 8)
void scan_kernel(const float* __restrict__ Whf, const float* __restrict__ Whb)
{
    const int pair = blockIdx.x;
    const int b = pair >> 1, dir = pair & 1;
    const int tid  = threadIdx.x;
    const int j    = tid >> 1;     // hidden row 0..63
    const int half = tid & 1;      // which 32-wide k chunk

    const float* W = dir ? Whb : Whf;
    float w[32];
    #pragma unroll
    for (int k = 0; k < 32; k += 4) {
        float4 v = *(const float4*)(W + j * 64 + half * 32 + k);
        w[k] = v.x; w[k + 1] = v.y; w[k + 2] = v.z; w[k + 3] = v.w;
    }

    __shared__ float hbuf[2][64];
    if (tid < 64) hbuf[0][tid] = 0.f;
    __syncthreads();

    const float* xpb = g_xp + (size_t)b * TT * 128 + dir * 64 + j;
    float*       ob  = g_h  + (size_t)b * TT * 128 + dir * 64 + j;

    float xq[4];
    #pragma unroll
    for (int i = 0; i < 4; i++) {
        int t = dir ? (TT - 1 - i) : i;
        xq[i] = __ldg(xpb + (size_t)t * 128);
    }

    int p = 0;
    for (int s4 = 0; s4 < TT / 4; s4++) {
        #pragma unroll
        for (int u = 0; u < 4; u++) {
            const int s = s4 * 4 + u;
            float x = xq[u];
            const int sp = s + 4;
            if (sp < TT) {
                int tp = dir ? (TT - 1 - sp) : sp;
                xq[u] = __ldg(xpb + (size_t)tp * 128);
            }
            float a0 = 0.f, a1 = 0.f, a2 = 0.f, a3 = 0.f;
            const float* hp = hbuf[p] + half * 32;
            #pragma unroll
            for (int k = 0; k < 32; k += 4) {
                float4 hv = *(const float4*)(hp + k);
                a0 = fmaf(w[k],     hv.x, a0);
                a1 = fmaf(w[k + 1], hv.y, a1);
                a2 = fmaf(w[k + 2], hv.z, a2);
                a3 = fmaf(w[k + 3], hv.w, a3);
            }
            float a = (a0 + a1) + (a2 + a3);
            a += __shfl_xor_sync(0xffffffffu, a, 1);
            float h = tanhf(x + a);
            int t = dir ? (TT - 1 - s) : s;
            if (half == 0) hbuf[p ^ 1][j] = h;       // smem update
            else           ob[(size_t)t * 128] = h;  // global store (off crit path)
            __syncthreads();
            p ^= 1;
        }
    }
}

// ---------------------------------------------------------------------------
// Kernel 3: head GEMM(128->32) + LayerNorm + ReLU + GEMM(32->4), fused.
// ---------------------------------------------------------------------------
#define HEAD_SMEM_FLOATS (128*132 + 128*36 + 128*33 + 128 + 32*3 + 4)

__global__ __launch_bounds__(256, 2)
void head_kernel(const float* __restrict__ W1, const float* __restrict__ b1,
                 const float* __restrict__ gamma, const float* __restrict__ beta,
                 const float* __restrict__ W2, const float* __restrict__ b2,
                 float* __restrict__ out)
{
    extern __shared__ float sm[];
    float* As  = sm;                    // [k][m]  128 x 132
    float* W1t = As + 128 * 132;        // [k][n]  128 x 36
    float* h1s = W1t + 128 * 36;        // [m][n]  128 x 33
    float* W2s = h1s + 128 * 33;        // 128
    float* b1s = W2s + 128;             // 32
    float* gms = b1s + 32;              // 32
    float* bts = gms + 32;              // 32
    float* b2s = bts + 32;              // 4

    const int tid = threadIdx.x;
    const int t0  = blockIdx.x * 128;

    #pragma unroll
    for (int i = 0; i < 16; i++) {      // W1t[k][n] = W1[n][k]
        int lin = tid + i * 256;
        int k = lin & 127, n = lin >> 7;
        W1t[k * 36 + n] = W1[n * 128 + k];
    }
    if (tid < 128) W2s[tid] = W2[tid];
    if (tid < 32) { b1s[tid] = b1[tid]; gms[tid] = gamma[tid]; bts[tid] = beta[tid]; }
    if (tid < 4)  b2s[tid] = b2[tid];

    #pragma unroll
    for (int i = 0; i < 16; i++) {      // As[k][m] = g_h[t0+m][k]
        int lin = tid + i * 256;
        int m = lin & 127, k4 = lin >> 7;
        float4 v = *(const float4*)(g_h + (size_t)(t0 + m) * 128 + k4 * 4);
        As[(k4 * 4 + 0) * 132 + m] = v.x;
        As[(k4 * 4 + 1) * 132 + m] = v.y;
        As[(k4 * 4 + 2) * 132 + m] = v.z;
        As[(k4 * 4 + 3) * 132 + m] = v.w;
    }
    __syncthreads();

    const int tt = tid >> 3;
    const int ot = tid & 7;
    float acc[4][4];
    #pragma unroll
    for (int i = 0; i < 4; i++)
        #pragma unroll
        for (int jx = 0; jx < 4; jx++) acc[i][jx] = 0.f;

    #pragma unroll 8
    for (int k = 0; k < 128; k++) {
        float4 av = *(const float4*)(As + k * 132 + tt * 4);
        float4 bv = *(const float4*)(W1t + k * 36 + ot * 4);
        acc[0][0] = fmaf(av.x, bv.x, acc[0][0]); acc[0][1] = fmaf(av.x, bv.y, acc[0][1]);
        acc[0][2] = fmaf(av.x, bv.z, acc[0][2]); acc[0][3] = fmaf(av.x, bv.w, acc[0][3]);
        acc[1][0] = fmaf(av.y, bv.x, acc[1][0]); acc[1][1] = fmaf(av.y, bv.y, acc[1][1]);
        acc[1][2] = fmaf(av.y, bv.z, acc[1][2]); acc[1][3] = fmaf(av.y, bv.w, acc[1][3]);
        acc[2][0] = fmaf(av.z, bv.x, acc[2][0]); acc[2][1] = fmaf(av.z, bv.y, acc[2][1]);
        acc[2][2] = fmaf(av.z, bv.z, acc[2][2]); acc[2][3] = fmaf(av.z, bv.w, acc[2][3]);
        acc[3][0] = fmaf(av.w, bv.x, acc[3][0]); acc[3][1] = fmaf(av.w, bv.y, acc[3][1]);
        acc[3][2] = fmaf(av.w, bv.z, acc[3][2]); acc[3][3] = fmaf(av.w, bv.w, acc[3][3]);
    }
    #pragma unroll
    for (int i = 0; i < 4; i++)
        #pragma unroll
        for (int jx = 0; jx < 4; jx++)
            h1s[(tt * 4 + i) * 33 + ot * 4 + jx] = acc[i][jx] + b1s[ot * 4 + jx];
    __syncthreads();

    if (tid < 128) {
        float h[32];
        #pragma unroll
        for (int i = 0; i < 32; i++) h[i] = h1s[tid * 33 + i];
        float s1 = 0.f, s2 = 0.f;
        #pragma unroll
        for (int i = 0; i < 32; i++) { s1 += h[i]; s2 = fmaf(h[i], h[i], s2); }
        float mu  = s1 * (1.f / 32.f);
        float var = s2 * (1.f / 32.f) - mu * mu;
        float inv = rsqrtf(var + 1e-5f);
        float o0 = b2s[0], o1 = b2s[1], o2 = b2s[2], o3 = b2s[3];
        #pragma unroll
        for (int i = 0; i < 32; i++) {
            float r = fmaf((h[i] - mu) * inv, gms[i], bts[i]);
            r = fmaxf(r, 0.f);
            o0 = fmaf(W2s[i],      r, o0);
            o1 = fmaf(W2s[32 + i], r, o1);
            o2 = fmaf(W2s[64 + i], r, o2);
            o3 = fmaf(W2s[96 + i], r, o3);
        }
        *(float4*)(out + (size_t)(t0 + tid) * 4) = make_float4(o0, o1, o2, o3);
    }
}

// ---------------------------------------------------------------------------
extern "C" void kernel_launch(void* const* d_in, const int* in_sizes, int n_in,
                              void* d_out, int out_size)
{
    const float* inputs = (const float*)d_in[0];
    const int*   posi   = (const int*)  d_in[1];
    const float* emb    = (const float*)d_in[2];
    const float* Wihf   = (const float*)d_in[3];
    const float* Whhf   = (const float*)d_in[4];
    const float* bihf   = (const float*)d_in[5];
    const float* bhhf   = (const float*)d_in[6];
    const float* Wihb   = (const float*)d_in[7];
    const float* Whhb   = (const float*)d_in[8];
    const float* bihb   = (const float*)d_in[9];
    const float* bhhb   = (const float*)d_in[10];
    const float* W1     = (const float*)d_in[11];
    const float* b1     = (const float*)d_in[12];
    const float* gamma  = (const float*)d_in[13];
    const float* beta   = (const float*)d_in[14];
    const float* W2     = (const float*)d_in[15];
    const float* b2     = (const float*)d_in[16];
    float* out = (float*)d_out;

    const int head_smem = HEAD_SMEM_FLOATS * (int)sizeof(float);
    cudaFuncSetAttribute(head_kernel, cudaFuncAttributeMaxDynamicSharedMemorySize, head_smem);

    prep_kernel<<<640, 128>>>(emb, Wihf, Wihb, bihf, bhhf, bihb, bhhb);
    gemm1_kernel<<<256, 256>>>(inputs, posi);
    scan_kernel<<<128, 128>>>(Whhf, Whhb);
    head_kernel<<<256, 256, head_smem>>>(W1, b1, gamma, beta, W2, b2, out);
}